// round 7
// baseline (speedup 1.0000x reference)
#include <cuda_runtime.h>
#include <cstdint>

// Problem constants (fixed by the reference)
#define B_ 16
#define H_ 100
#define W_ 100
#define C_ 256
#define R_ 128
#define P_ 7
#define CELLS (P_ * P_)   // 49

__device__ __forceinline__ float4 lerp4(float4 a, float4 b, float4 c, float4 d,
                                        float fx, float fy)
{
    float4 o;
    float top, bot;
    top = a.x + (b.x - a.x) * fx;  bot = c.x + (d.x - c.x) * fx;  o.x = top + (bot - top) * fy;
    top = a.y + (b.y - a.y) * fx;  bot = c.y + (d.y - c.y) * fx;  o.y = top + (bot - top) * fy;
    top = a.z + (b.z - a.z) * fx;  bot = c.z + (d.z - c.z) * fx;  o.z = top + (bot - top) * fy;
    top = a.w + (b.w - a.w) * fx;  bot = c.w + (d.w - c.w) * fx;  o.w = top + (bot - top) * fy;
    return o;
}

__device__ __forceinline__ float4 ldcg4(const float4* p)
{
    float4 v;
    asm volatile("ld.global.cg.v4.f32 {%0,%1,%2,%3}, [%4];"
                 : "=f"(v.x), "=f"(v.y), "=f"(v.z), "=f"(v.w) : "l"(p));
    return v;
}

// One CTA per ROI. Phase 1: threads 0..48 compute the bilinear tuple for one
// output cell each into smem. Phase 2: 256 threads = (4 cell-lanes) x (64
// float4 channel groups); each lane walks cells sub+4k (k=0..11) with the
// NEXT iteration's smem tuple prefetched into registers so the LDS latency
// stays off the LDG critical path. Regs pinned to 32 via launch_bounds.
__global__ __launch_bounds__(256, 8) void roi_pool_kernel(
    const float* __restrict__ fm,   // [B, H, W, C]
    const int*   __restrict__ rois, // [B, R, 4]  (x, y, h, w)
    float*       __restrict__ out)  // [B, R, P, P, C]
{
    __shared__ int4   s_off[CELLS];   // float4-unit offsets of the 4 corners
    __shared__ float2 s_fr[CELLS];    // (fx, fy)

    const int roi_idx = blockIdx.x;        // b*R + r
    const int b = roi_idx >> 7;            // R_ = 128
    const int tid = threadIdx.x;

    if (tid < CELLS) {
        const int4 roi = __ldg((const int4*)(rois + (size_t)roi_idx * 4));
        const int x = roi.x, y = roi.y, h = roi.z, w = roi.w;

        const int py = tid / P_;
        const int px = tid - py * P_;

        // y axis: src = (py+0.5)/P * h - 0.5, clipped to [0, h-1]
        const float hf = (float)h;
        float sy = ((float)py + 0.5f) * (1.0f / P_) * hf - 0.5f;
        sy = fminf(fmaxf(sy, 0.0f), hf - 1.0f);
        int   y0 = (int)floorf(sy);
        const float fy = sy - (float)y0;
        y0 += y;
        const int y1 = min(y0 + 1, y + h - 1);

        // x axis
        const float wf = (float)w;
        float sx = ((float)px + 0.5f) * (1.0f / P_) * wf - 0.5f;
        sx = fminf(fmaxf(sx, 0.0f), wf - 1.0f);
        int   x0 = (int)floorf(sx);
        const float fx = sx - (float)x0;
        x0 += x;
        const int x1 = min(x0 + 1, x + w - 1);

        // offsets in float4 units (C_/4 = 64 per pixel row)
        s_off[tid] = make_int4((y0 * W_ + x0) * (C_ / 4),
                               (y0 * W_ + x1) * (C_ / 4),
                               (y1 * W_ + x0) * (C_ / 4),
                               (y1 * W_ + x1) * (C_ / 4));
        s_fr[tid] = make_float2(fx, fy);
    }
    __syncthreads();

    const int c4  = tid & 63;     // float4 channel group 0..63
    const int sub = tid >> 6;     // cell lane 0..3

    const float4* base  = (const float4*)(fm + (size_t)b * (H_ * W_ * C_)) + c4;
    float4*       obase = (float4*)(out + (size_t)roi_idx * (CELLS * C_)) + c4;

    // Tuple for the first cell.
    int4   off = s_off[sub];
    float2 fr  = s_fr[sub];

    // Lane `sub` covers cells sub, sub+4, ..., sub+44 (12 cells).
    #pragma unroll
    for (int k = 0; k < 12; k++) {
        const int cell = sub + k * 4;

        // Prefetch next tuple before touching this cell's data.
        int4   noff;
        float2 nfr;
        if (k < 11) {
            noff = s_off[cell + 4];
            nfr  = s_fr[cell + 4];
        }

        const float4 a = ldcg4(base + off.x);
        const float4 bq = ldcg4(base + off.y);
        const float4 c = ldcg4(base + off.z);
        const float4 d = ldcg4(base + off.w);

        __stcs(obase + cell * (C_ / 4), lerp4(a, bq, c, d, fr.x, fr.y));

        if (k < 11) { off = noff; fr = nfr; }
    }

    // Remainder: cell 48 (lane 0 only).
    if (sub == 0) {
        const int4   roff = s_off[48];
        const float2 rfr  = s_fr[48];
        const float4 ra = ldcg4(base + roff.x);
        const float4 rb = ldcg4(base + roff.y);
        const float4 rc = ldcg4(base + roff.z);
        const float4 rd = ldcg4(base + roff.w);
        __stcs(obase + 48 * (C_ / 4), lerp4(ra, rb, rc, rd, rfr.x, rfr.y));
    }
}

extern "C" void kernel_launch(void* const* d_in, const int* in_sizes, int n_in,
                              void* d_out, int out_size)
{
    const float* fm   = (const float*)d_in[0];
    const int*   rois = (const int*)d_in[1];
    float*       out  = (float*)d_out;

    roi_pool_kernel<<<B_ * R_, 256>>>(fm, rois, out);
}